// round 7
// baseline (speedup 1.0000x reference)
#include <cuda_runtime.h>

// ---------------------------------------------------------------------------
// Persistent fused LSTM: T=2048, B=256, H=128, IN_DIM=1, output feedback.
// 128 CTAs x 256 threads; CTA c owns batches (2c, 2c+1).
// UNIT-OWNER mapping: thread (p = t>>1, ks = t&1) computes gate rows
// {p, 128+p, 256+p, 384+p} (i,f,g,o of hidden unit p), k-half ks, for BOTH
// batches. One shfl.xor(1) per gate completes the sum; the same thread then
// updates (batch=ks, j=p). Rows {p,128+p} weights in registers (f32x2-packed),
// rows {256+p,384+p} streamed from bank-exact SMEM. ONE barrier per step;
// HBUF parity double-buffered, YBUF 2-slot.
// ---------------------------------------------------------------------------

typedef unsigned long long ull;

#define THREADS 256
#define T_STEPS 2048
#define NB      256

// SMEM layout (float offsets)
#define KH       68                    // k-half stride (64 + 4 pad)
#define W_PITCH  136                   // weight row pitch (2*68) -> lanes hit granules 0..7
#define WS_OFF   0                     // 256 rows (g,o gates) x 136 = 34816
#define HBUF     34816                 // [2 parity][2 batch x 144]
#define HB_B     144                   // batch stride (=16 mod 32 -> STS conflict-free)
#define HB_PAR   288
#define YBUF     (HBUF + 2*HB_PAR)     // [2 slot][2 batch][16]
#define SMEM_FLOATS (YBUF + 64)
#define SMEM_BYTES  (SMEM_FLOATS * 4)

__device__ __forceinline__ ull pk2(float x, float y) {
    ull r; asm("mov.b64 %0, {%1, %2};" : "=l"(r) : "f"(x), "f"(y)); return r;
}
__device__ __forceinline__ float2 upk2(ull v) {
    float2 f; asm("mov.b64 {%0, %1}, %2;" : "=f"(f.x), "=f"(f.y) : "l"(v)); return f;
}
__device__ __forceinline__ ull ffma2(ull a, ull b, ull c) {
    ull d; asm("fma.rn.f32x2 %0, %1, %2, %3;" : "=l"(d) : "l"(a), "l"(b), "l"(c)); return d;
}
__device__ __forceinline__ float sigf(float x)  { return __fdividef(1.0f, 1.0f + __expf(-x)); }
__device__ __forceinline__ float tanhx(float x) { return __fdividef(2.0f, 1.0f + __expf(-2.0f * x)) - 1.0f; }

__global__ void __launch_bounds__(THREADS, 1)
lstm_seq_kernel(float* __restrict__ out,
                const int*   __restrict__ label,
                const float* __restrict__ h0,
                const float* __restrict__ W_ih,
                const float* __restrict__ W_hh,
                const float* __restrict__ b_ih,
                const float* __restrict__ b_hh,
                const float* __restrict__ W_lin,
                const float* __restrict__ b_lin)
{
    extern __shared__ float sm[];
    const int t    = threadIdx.x;
    const int cta  = blockIdx.x;
    const int p    = t >> 1;      // hidden unit 0..127
    const int ks   = t & 1;       // k half (also: batch this thread updates)
    const int lane = t & 31;

    // ---- one-time init -----------------------------------------------------
    // SMEM weights: global rows 256..511 (g,o gates)
    for (int idx = t; idx < 256 * 128; idx += THREADS) {
        int r = idx >> 7, k = idx & 127;
        sm[WS_OFF + r * W_PITCH + (k >> 6) * KH + (k & 63)] = W_hh[(256 + r) * 128 + k];
    }
    {   // initial h -> parity 0
        int b = t >> 7, j = t & 127;
        int lab = label[2 * cta + b];
        sm[HBUF + b * HB_B + (j >> 6) * KH + (j & 63)] = h0[lab * 128 + j];
    }

    // Register weights: rows p (i gate) and 128+p (f gate), k-half ks.
    ull wri[32], wrf[32];
    {
        const float2* s0 = (const float2*)(W_hh + p * 128 + ks * 64);
        const float2* s1 = (const float2*)(W_hh + (128 + p) * 128 + ks * 64);
#pragma unroll
        for (int c = 0; c < 32; ++c) {
            float2 a = s0[c], b = s1[c];
            wri[c] = pk2(a.x, a.y);
            wrf[c] = pk2(b.x, b.y);
        }
    }

    // per-unit constants in registers
    float biasv[4], wihv[4];
    {
        int rows[4] = {p, 128 + p, 256 + p, 384 + p};
#pragma unroll
        for (int q = 0; q < 4; ++q) {
            biasv[q] = b_ih[rows[q]] + b_hh[rows[q]];
            wihv[q]  = W_ih[rows[q]];
        }
    }
    const float wlin_p = W_lin[p];
    const float blin   = b_lin[0];
    float c_state = 0.0f;                 // cell state for (batch=ks, j=p)

    // matvec pointers, both parities
    const ulonglong2* H0a = (const ulonglong2*)(sm + HBUF + ks * KH);              // b0, par0
    const ulonglong2* H1a = (const ulonglong2*)(sm + HBUF + HB_B + ks * KH);       // b1, par0
    const ulonglong2* H0b = (const ulonglong2*)(sm + HBUF + HB_PAR + ks * KH);
    const ulonglong2* H1b = (const ulonglong2*)(sm + HBUF + HB_PAR + HB_B + ks * KH);
    const ulonglong2* W2  = (const ulonglong2*)(sm + WS_OFF + p * W_PITCH + ks * KH);          // g row
    const ulonglong2* W3  = (const ulonglong2*)(sm + WS_OFF + (128 + p) * W_PITCH + ks * KH);  // o row
    // hn store addresses, both parities (this thread owns (b=ks, j=p))
    const int hwrA = HBUF + ks * HB_B + (p >> 6) * KH + (p & 63);
    const int hwrB = hwrA + HB_PAR;

    __syncthreads();

    // ---- 2048-step recurrence: ONE barrier per step -------------------------
    for (int step = 0; step < T_STEPS; ++step) {
        const int par = step & 1;

        // x feedback: fold previous step's y partials (this thread's batch)
        float xb = 0.0f;
        if (step > 0) {
            const float4* yb = (const float4*)(sm + YBUF + par * 32 + ks * 16);
            float4 y0 = yb[0], y1 = yb[1], y2 = yb[2], y3 = yb[3];
            xb = ((y0.x + y0.y) + (y0.z + y0.w)) + ((y1.x + y1.y) + (y1.z + y1.w))
               + ((y2.x + y2.y) + (y2.z + y2.w)) + ((y3.x + y3.y) + (y3.z + y3.w)) + blin;
            if (p == 0) out[(step - 1) * NB + 2 * cta + ks] = xb;
        }

        // ====== matvec: 4 gate rows x 2 batches, this k-half ======
        const ulonglong2* H0 = par ? H0b : H0a;
        const ulonglong2* H1 = par ? H1b : H1a;
        ull ai0 = 0, ai1 = 0, af0 = 0, af1 = 0, ag0 = 0, ag1 = 0, ao0 = 0, ao1 = 0;

#pragma unroll
        for (int c = 0; c < 16; ++c) {
            ulonglong2 hv0 = H0[c];
            ulonglong2 hv1 = H1[c];
            ulonglong2 w2  = W2[c];
            ulonglong2 w3  = W3[c];
            ull wia = wri[2 * c], wib = wri[2 * c + 1];
            ull wfa = wrf[2 * c], wfb = wrf[2 * c + 1];

            ai0 = ffma2(wia, hv0.x, ai0); ai0 = ffma2(wib, hv0.y, ai0);
            ai1 = ffma2(wia, hv1.x, ai1); ai1 = ffma2(wib, hv1.y, ai1);
            af0 = ffma2(wfa, hv0.x, af0); af0 = ffma2(wfb, hv0.y, af0);
            af1 = ffma2(wfa, hv1.x, af1); af1 = ffma2(wfb, hv1.y, af1);
            ag0 = ffma2(w2.x, hv0.x, ag0); ag0 = ffma2(w2.y, hv0.y, ag0);
            ag1 = ffma2(w2.x, hv1.x, ag1); ag1 = ffma2(w2.y, hv1.y, ag1);
            ao0 = ffma2(w3.x, hv0.x, ao0); ao0 = ffma2(w3.y, hv0.y, ao0);
            ao1 = ffma2(w3.x, hv1.x, ao1); ao1 = ffma2(w3.y, hv1.y, ao1);
        }

        // fold f32x2 + exchange k-halves with partner lane (t^1, same p):
        // lane keeps batch==ks, ships its other-batch partial to the partner.
        float gI, gF, gG, gO;
        {
            float2 f;
            f = upk2(ai0); float si0 = f.x + f.y;
            f = upk2(ai1); float si1 = f.x + f.y;
            f = upk2(af0); float sf0 = f.x + f.y;
            f = upk2(af1); float sf1 = f.x + f.y;
            f = upk2(ag0); float sg0 = f.x + f.y;
            f = upk2(ag1); float sg1 = f.x + f.y;
            f = upk2(ao0); float so0 = f.x + f.y;
            f = upk2(ao1); float so1 = f.x + f.y;
            gI = (ks ? si1 : si0) + __shfl_xor_sync(0xffffffffu, ks ? si0 : si1, 1);
            gF = (ks ? sf1 : sf0) + __shfl_xor_sync(0xffffffffu, ks ? sf0 : sf1, 1);
            gG = (ks ? sg1 : sg0) + __shfl_xor_sync(0xffffffffu, ks ? sg0 : sg1, 1);
            gO = (ks ? so1 : so0) + __shfl_xor_sync(0xffffffffu, ks ? so0 : so1, 1);
        }

        // ====== update (batch=ks, j=p), all in registers ======
        {
            gI += fmaf(xb, wihv[0], biasv[0]);
            gF += fmaf(xb, wihv[1], biasv[1]);
            gG += fmaf(xb, wihv[2], biasv[2]);
            gO += fmaf(xb, wihv[3], biasv[3]);
            float iv = sigf(gI);
            float fv = sigf(gF);
            float gv = tanhx(gG);
            float ov = sigf(gO);
            c_state = fv * c_state + iv * gv;
            float hn = ov * tanhx(c_state);
            sm[par ? hwrA : hwrB] = hn;          // write next parity

            // y partial: 3-level shfl within batch parity (8-lane groups)
            float py = hn * wlin_p;
            py += __shfl_xor_sync(0xffffffffu, py, 2);
            py += __shfl_xor_sync(0xffffffffu, py, 4);
            py += __shfl_xor_sync(0xffffffffu, py, 8);
            if ((lane & 14) == 0)   // lanes 0,1,16,17
                sm[YBUF + (par ^ 1) * 32 + ks * 16 + (t >> 5) * 2 + (lane >> 4)] = py;
        }
        __syncthreads();   // next parity HBUF + YBUF visible
    }

    // final output y_{T-1} (in YBUF slot (T_STEPS & 1) = 0)
    if (t < 2) {
        const float* yb = sm + YBUF + (T_STEPS & 1) * 32 + ks * 16;
        float y = blin;
#pragma unroll
        for (int i = 0; i < 16; ++i) y += yb[i];
        out[(T_STEPS - 1) * NB + 2 * cta + ks] = y;
    }
}

extern "C" void kernel_launch(void* const* d_in, const int* in_sizes, int n_in,
                              void* d_out, int out_size) {
    // metadata order: input, label, h0, W_ih, W_hh, b_ih, b_hh, W_lin, b_lin
    const int*   label  = (const int*)  d_in[1];
    const float* h0     = (const float*)d_in[2];
    const float* W_ih   = (const float*)d_in[3];
    const float* W_hh   = (const float*)d_in[4];
    const float* b_ih   = (const float*)d_in[5];
    const float* b_hh   = (const float*)d_in[6];
    const float* W_lin  = (const float*)d_in[7];
    const float* b_lin  = (const float*)d_in[8];
    float* out = (float*)d_out;

    cudaFuncSetAttribute(lstm_seq_kernel,
                         cudaFuncAttributeMaxDynamicSharedMemorySize, SMEM_BYTES);
    lstm_seq_kernel<<<128, THREADS, SMEM_BYTES>>>(out, label, h0, W_ih, W_hh,
                                                  b_ih, b_hh, W_lin, b_lin);
}

// round 8
// speedup vs baseline: 1.0847x; 1.0847x over previous
#include <cuda_runtime.h>

// ---------------------------------------------------------------------------
// Persistent fused LSTM, feedback algebraically absorbed:
//   W_eff = W_hh + W_ih (outer) W_lin,  b_eff = b_ih + b_hh + W_ih * b_lin
//   gates_t = W_eff . h_{t-1} + b_eff   (exact; step 0 corrected by xb0)
// 128 CTAs x 256 threads; CTA owns batches (2c, 2c+1).
// Unit-owner mapping: thread (p=t>>1, ks=t&1) computes gates {i,f,g,o} of
// unit p, k-half ks, both batches; xor1 with partner completes sums; same
// thread updates (batch=ks, j=p). i,f weights in regs (f32x2), g,o in SMEM.
// ONE barrier/step. tanh.approx.f32 activations. y off the critical path.
// ---------------------------------------------------------------------------

typedef unsigned long long ull;

#define THREADS 256
#define T_STEPS 2048
#define NB      256

// SMEM layout (float offsets)
#define KH       68                    // k-half stride (64 + 4 pad)
#define W_PITCH  136                   // weight row pitch -> LDS phases hit granules 0..7
#define WS_OFF   0                     // 256 rows (g,o gates) x 136 = 34816
#define HBUF     34816                 // [2 parity][2 batch x 144]
#define HB_B     144
#define HB_PAR   288
#define YBUF     (HBUF + 2*HB_PAR)     // [2 slot][2 batch][16]
#define SMEM_FLOATS (YBUF + 64)
#define SMEM_BYTES  (SMEM_FLOATS * 4)

__device__ __forceinline__ ull pk2(float x, float y) {
    ull r; asm("mov.b64 %0, {%1, %2};" : "=l"(r) : "f"(x), "f"(y)); return r;
}
__device__ __forceinline__ float2 upk2(ull v) {
    float2 f; asm("mov.b64 {%0, %1}, %2;" : "=f"(f.x), "=f"(f.y) : "l"(v)); return f;
}
__device__ __forceinline__ ull ffma2(ull a, ull b, ull c) {
    ull d; asm("fma.rn.f32x2 %0, %1, %2, %3;" : "=l"(d) : "l"(a), "l"(b), "l"(c)); return d;
}
__device__ __forceinline__ float tanha(float x) {
    float y; asm("tanh.approx.f32 %0, %1;" : "=f"(y) : "f"(x)); return y;
}
__device__ __forceinline__ float siga(float x) {   // sigmoid via tanh identity
    return fmaf(0.5f, tanha(0.5f * x), 0.5f);
}

__global__ void __launch_bounds__(THREADS, 1)
lstm_seq_kernel(float* __restrict__ out,
                const int*   __restrict__ label,
                const float* __restrict__ h0,
                const float* __restrict__ W_ih,
                const float* __restrict__ W_hh,
                const float* __restrict__ b_ih,
                const float* __restrict__ b_hh,
                const float* __restrict__ W_lin,
                const float* __restrict__ b_lin)
{
    extern __shared__ float sm[];
    const int t    = threadIdx.x;
    const int cta  = blockIdx.x;
    const int p    = t >> 1;      // hidden unit 0..127
    const int ks   = t & 1;       // k half == batch this thread updates
    const int lane = t & 31;
    const float blin = b_lin[0];

    // ---- one-time init -----------------------------------------------------
    // SMEM weights: effective rows 256..511 (g,o gates), rank-1 folded in
    for (int idx = t; idx < 256 * 128; idx += THREADS) {
        int r = idx >> 7, k = idx & 127;
        sm[WS_OFF + r * W_PITCH + (k >> 6) * KH + (k & 63)] =
            W_hh[(256 + r) * 128 + k] + W_ih[256 + r] * W_lin[k];
    }
    {   // initial h -> parity 0
        int b = t >> 7, j = t & 127;
        int lab = label[2 * cta + b];
        sm[HBUF + b * HB_B + (j >> 6) * KH + (j & 63)] = h0[lab * 128 + j];
    }

    // Register weights: effective rows p (i) and 128+p (f), k-half ks.
    ull wri[32], wrf[32];
    {
        const float2* s0 = (const float2*)(W_hh + p * 128 + ks * 64);
        const float2* s1 = (const float2*)(W_hh + (128 + p) * 128 + ks * 64);
        const float2* wl = (const float2*)(W_lin + ks * 64);
        const float wih_i = W_ih[p], wih_f = W_ih[128 + p];
#pragma unroll
        for (int c = 0; c < 32; ++c) {
            float2 a = s0[c], b = s1[c], w = wl[c];
            wri[c] = pk2(fmaf(wih_i, w.x, a.x), fmaf(wih_i, w.y, a.y));
            wrf[c] = pk2(fmaf(wih_f, w.x, b.x), fmaf(wih_f, w.y, b.y));
        }
    }

    // per-unit constants: b_eff and W_ih (latter used only for step-0 fix)
    float biasv[4], wihv[4];
    {
        int rows[4] = {p, 128 + p, 256 + p, 384 + p};
#pragma unroll
        for (int q = 0; q < 4; ++q) {
            wihv[q]  = W_ih[rows[q]];
            biasv[q] = b_ih[rows[q]] + b_hh[rows[q]] + wihv[q] * blin;
        }
    }
    const float wlin_p = W_lin[p];
    float c_state = 0.0f;

    __syncthreads();

    // step-0 correction: xb0 = -(W_lin . h_init[ks] + b_lin)
    float xb;
    {
        float acc = 0.0f;
        const float* hb = sm + HBUF + ks * HB_B;
#pragma unroll 8
        for (int j = 0; j < 128; ++j)
            acc = fmaf(hb[(j >> 6) * KH + (j & 63)], W_lin[j], acc);
        xb = -(acc + blin);
    }

    // matvec pointers, both parities
    const ulonglong2* H0a = (const ulonglong2*)(sm + HBUF + ks * KH);
    const ulonglong2* H1a = (const ulonglong2*)(sm + HBUF + HB_B + ks * KH);
    const ulonglong2* H0b = (const ulonglong2*)(sm + HBUF + HB_PAR + ks * KH);
    const ulonglong2* H1b = (const ulonglong2*)(sm + HBUF + HB_PAR + HB_B + ks * KH);
    const ulonglong2* W2  = (const ulonglong2*)(sm + WS_OFF + p * W_PITCH + ks * KH);
    const ulonglong2* W3  = (const ulonglong2*)(sm + WS_OFF + (128 + p) * W_PITCH + ks * KH);
    const int hwrA = HBUF + ks * HB_B + (p >> 6) * KH + (p & 63);
    const int hwrB = hwrA + HB_PAR;

    // ---- 2048-step recurrence: ONE barrier per step -------------------------
    for (int step = 0; step < T_STEPS; ++step) {
        const int par = step & 1;

        // output store for previous step (off critical path; p==0 only)
        if (p == 0 && step > 0) {
            const float* yb = sm + YBUF + par * 32 + ks * 16;
            float y = blin;
#pragma unroll
            for (int i = 0; i < 16; ++i) y += yb[i];
            out[(step - 1) * NB + 2 * cta + ks] = y;
        }

        // ====== matvec: 4 gate rows x 2 batches, this k-half ======
        const ulonglong2* H0 = par ? H0b : H0a;
        const ulonglong2* H1 = par ? H1b : H1a;
        ull ai0 = 0, ai1 = 0, af0 = 0, af1 = 0, ag0 = 0, ag1 = 0, ao0 = 0, ao1 = 0;

#pragma unroll
        for (int c = 0; c < 16; ++c) {
            ulonglong2 hv0 = H0[c];
            ulonglong2 hv1 = H1[c];
            ulonglong2 w2  = W2[c];
            ulonglong2 w3  = W3[c];
            ull wia = wri[2 * c], wib = wri[2 * c + 1];
            ull wfa = wrf[2 * c], wfb = wrf[2 * c + 1];

            ai0 = ffma2(wia, hv0.x, ai0); ai0 = ffma2(wib, hv0.y, ai0);
            ai1 = ffma2(wia, hv1.x, ai1); ai1 = ffma2(wib, hv1.y, ai1);
            af0 = ffma2(wfa, hv0.x, af0); af0 = ffma2(wfb, hv0.y, af0);
            af1 = ffma2(wfa, hv1.x, af1); af1 = ffma2(wfb, hv1.y, af1);
            ag0 = ffma2(w2.x, hv0.x, ag0); ag0 = ffma2(w2.y, hv0.y, ag0);
            ag1 = ffma2(w2.x, hv1.x, ag1); ag1 = ffma2(w2.y, hv1.y, ag1);
            ao0 = ffma2(w3.x, hv0.x, ao0); ao0 = ffma2(w3.y, hv0.y, ao0);
            ao1 = ffma2(w3.x, hv1.x, ao1); ao1 = ffma2(w3.y, hv1.y, ao1);
        }

        // fold f32x2 + exchange k-halves with partner lane (t^1, same p)
        float gI, gF, gG, gO;
        {
            float2 f;
            f = upk2(ai0); float si0 = f.x + f.y;
            f = upk2(ai1); float si1 = f.x + f.y;
            f = upk2(af0); float sf0 = f.x + f.y;
            f = upk2(af1); float sf1 = f.x + f.y;
            f = upk2(ag0); float sg0 = f.x + f.y;
            f = upk2(ag1); float sg1 = f.x + f.y;
            f = upk2(ao0); float so0 = f.x + f.y;
            f = upk2(ao1); float so1 = f.x + f.y;
            gI = (ks ? si1 : si0) + __shfl_xor_sync(0xffffffffu, ks ? si0 : si1, 1);
            gF = (ks ? sf1 : sf0) + __shfl_xor_sync(0xffffffffu, ks ? sf0 : sf1, 1);
            gG = (ks ? sg1 : sg0) + __shfl_xor_sync(0xffffffffu, ks ? sg0 : sg1, 1);
            gO = (ks ? so1 : so0) + __shfl_xor_sync(0xffffffffu, ks ? so0 : so1, 1);
        }

        // ====== update (batch=ks, j=p) ======
        {
            gI += fmaf(xb, wihv[0], biasv[0]);   // xb nonzero only at step 0
            gF += fmaf(xb, wihv[1], biasv[1]);
            gG += fmaf(xb, wihv[2], biasv[2]);
            gO += fmaf(xb, wihv[3], biasv[3]);
            float iv = siga(gI);
            float fv = siga(gF);
            float gv = tanha(gG);
            float ov = siga(gO);
            c_state = fv * c_state + iv * gv;
            float hn = ov * tanha(c_state);
            sm[par ? hwrA : hwrB] = hn;          // next-parity h

            // y partial for output (nothing on the recurrence waits on this)
            float py = hn * wlin_p;
            py += __shfl_xor_sync(0xffffffffu, py, 2);
            py += __shfl_xor_sync(0xffffffffu, py, 4);
            py += __shfl_xor_sync(0xffffffffu, py, 8);
            if ((lane & 14) == 0)   // lanes 0,1,16,17
                sm[YBUF + (par ^ 1) * 32 + ks * 16 + (t >> 5) * 2 + (lane >> 4)] = py;
        }
        xb = 0.0f;
        __syncthreads();   // next parity HBUF (+ YBUF) visible
    }

    // final output y_{T-1}
    if (p == 0) {
        const float* yb = sm + YBUF + (T_STEPS & 1) * 32 + ks * 16;
        float y = blin;
#pragma unroll
        for (int i = 0; i < 16; ++i) y += yb[i];
        out[(T_STEPS - 1) * NB + 2 * cta + ks] = y;
    }
}

extern "C" void kernel_launch(void* const* d_in, const int* in_sizes, int n_in,
                              void* d_out, int out_size) {
    // metadata order: input, label, h0, W_ih, W_hh, b_ih, b_hh, W_lin, b_lin
    const int*   label  = (const int*)  d_in[1];
    const float* h0     = (const float*)d_in[2];
    const float* W_ih   = (const float*)d_in[3];
    const float* W_hh   = (const float*)d_in[4];
    const float* b_ih   = (const float*)d_in[5];
    const float* b_hh   = (const float*)d_in[6];
    const float* W_lin  = (const float*)d_in[7];
    const float* b_lin  = (const float*)d_in[8];
    float* out = (float*)d_out;

    cudaFuncSetAttribute(lstm_seq_kernel,
                         cudaFuncAttributeMaxDynamicSharedMemorySize, SMEM_BYTES);
    lstm_seq_kernel<<<128, THREADS, SMEM_BYTES>>>(out, label, h0, W_ih, W_hh,
                                                  b_ih, b_hh, W_lin, b_lin);
}

// round 9
// speedup vs baseline: 1.1381x; 1.0492x over previous
#include <cuda_runtime.h>

// ---------------------------------------------------------------------------
// Persistent fused LSTM, feedback algebraically absorbed:
//   W_eff = W_hh + W_ih (outer) W_lin,  b_eff = b_ih + b_hh + W_ih * b_lin
// 128 CTAs x 256 threads; CTA owns batches (2c, 2c+1).
// Unit-owner mapping: thread (p=t>>1, ks=t&1) computes gates {i,f,g,o} of
// unit p, k-half ks, both batches; xor1 completes sums; same thread updates
// (batch=ks, j=p). i,f weights in regs (f32x2), g,o in SMEM. ONE barrier/step.
// R8: y-reduction deferred past the barrier (overlaps next step's LDS),
// out[s] stored at step s+2 via 2-slot YBUF; parity pointers per-step.
// ---------------------------------------------------------------------------

typedef unsigned long long ull;

#define THREADS 256
#define T_STEPS 2048
#define NB      256

// SMEM layout (float offsets)
#define KH       68                    // k-half stride (64 + 4 pad)
#define W_PITCH  136                   // weight row pitch -> LDS phases hit granules 0..7
#define WS_OFF   0                     // 256 rows (g,o gates) x 136 = 34816
#define HBUF     34816                 // [2 parity][2 batch x 144]
#define HB_B     144
#define HB_PAR   288
#define YBUF     (HBUF + 2*HB_PAR)     // [2 slot][2 batch][16]
#define SMEM_FLOATS (YBUF + 64)
#define SMEM_BYTES  (SMEM_FLOATS * 4)

__device__ __forceinline__ ull pk2(float x, float y) {
    ull r; asm("mov.b64 %0, {%1, %2};" : "=l"(r) : "f"(x), "f"(y)); return r;
}
__device__ __forceinline__ float2 upk2(ull v) {
    float2 f; asm("mov.b64 {%0, %1}, %2;" : "=f"(f.x), "=f"(f.y) : "l"(v)); return f;
}
__device__ __forceinline__ ull ffma2(ull a, ull b, ull c) {
    ull d; asm("fma.rn.f32x2 %0, %1, %2, %3;" : "=l"(d) : "l"(a), "l"(b), "l"(c)); return d;
}
__device__ __forceinline__ float tanha(float x) {
    float y; asm("tanh.approx.f32 %0, %1;" : "=f"(y) : "f"(x)); return y;
}
__device__ __forceinline__ float siga(float x) {
    return fmaf(0.5f, tanha(0.5f * x), 0.5f);
}

__global__ void __launch_bounds__(THREADS, 1)
lstm_seq_kernel(float* __restrict__ out,
                const int*   __restrict__ label,
                const float* __restrict__ h0,
                const float* __restrict__ W_ih,
                const float* __restrict__ W_hh,
                const float* __restrict__ b_ih,
                const float* __restrict__ b_hh,
                const float* __restrict__ W_lin,
                const float* __restrict__ b_lin)
{
    extern __shared__ float sm[];
    const int t    = threadIdx.x;
    const int cta  = blockIdx.x;
    const int p    = t >> 1;      // hidden unit 0..127
    const int ks   = t & 1;       // k half == batch this thread updates
    const int lane = t & 31;
    const float blin = b_lin[0];

    // ---- one-time init -----------------------------------------------------
    // SMEM weights: effective rows 256..511 (g,o gates), rank-1 folded in
    for (int idx = t; idx < 256 * 128; idx += THREADS) {
        int r = idx >> 7, k = idx & 127;
        sm[WS_OFF + r * W_PITCH + (k >> 6) * KH + (k & 63)] =
            W_hh[(256 + r) * 128 + k] + W_ih[256 + r] * W_lin[k];
    }
    {   // initial h -> parity 0
        int b = t >> 7, j = t & 127;
        int lab = label[2 * cta + b];
        sm[HBUF + b * HB_B + (j >> 6) * KH + (j & 63)] = h0[lab * 128 + j];
    }

    // Register weights: effective rows p (i) and 128+p (f), k-half ks.
    ull wri[32], wrf[32];
    {
        const float2* s0 = (const float2*)(W_hh + p * 128 + ks * 64);
        const float2* s1 = (const float2*)(W_hh + (128 + p) * 128 + ks * 64);
        const float2* wl = (const float2*)(W_lin + ks * 64);
        const float wih_i = W_ih[p], wih_f = W_ih[128 + p];
#pragma unroll
        for (int c = 0; c < 32; ++c) {
            float2 a = s0[c], b = s1[c], w = wl[c];
            wri[c] = pk2(fmaf(wih_i, w.x, a.x), fmaf(wih_i, w.y, a.y));
            wrf[c] = pk2(fmaf(wih_f, w.x, b.x), fmaf(wih_f, w.y, b.y));
        }
    }

    // per-unit constants
    float biasv[4], wihv[4];
    {
        int rows[4] = {p, 128 + p, 256 + p, 384 + p};
#pragma unroll
        for (int q = 0; q < 4; ++q) {
            wihv[q]  = W_ih[rows[q]];
            biasv[q] = b_ih[rows[q]] + b_hh[rows[q]] + wihv[q] * blin;
        }
    }
    const float wlin_p = W_lin[p];
    float c_state = 0.0f;
    float hn_prev = 0.0f;

    __syncthreads();

    // step-0 correction: xb0 = -(W_lin . h_init[ks] + b_lin)
    float xb;
    {
        float acc = 0.0f;
        const float* hb = sm + HBUF + ks * HB_B;
#pragma unroll 8
        for (int j = 0; j < 128; ++j)
            acc = fmaf(hb[(j >> 6) * KH + (j & 63)], W_lin[j], acc);
        xb = -(acc + blin);
    }

    // constant pointers
    const ulonglong2* W2 = (const ulonglong2*)(sm + WS_OFF + p * W_PITCH + ks * KH);
    const ulonglong2* W3 = (const ulonglong2*)(sm + WS_OFF + (128 + p) * W_PITCH + ks * KH);
    const int hwr0 = HBUF + ks * HB_B + (p >> 6) * KH + (p & 63);

    // ---- 2048-step recurrence: ONE barrier per step -------------------------
    for (int step = 0; step < T_STEPS; ++step) {
        const int par = step & 1;

        // (A) y-reduction for PREVIOUS step's h — overlaps the matvec's LDS
        if (step > 0) {
            float py = hn_prev * wlin_p;
            py += __shfl_xor_sync(0xffffffffu, py, 2);
            py += __shfl_xor_sync(0xffffffffu, py, 4);
            py += __shfl_xor_sync(0xffffffffu, py, 8);
            if ((lane & 14) == 0)   // lanes 0,1,16,17
                sm[YBUF + ((step - 1) & 1) * 32 + ks * 16 + (t >> 5) * 2 + (lane >> 4)] = py;
        }
        // (B) out-store for step-2 (slot (step-2)&1 == step&1; off critical path)
        if (p == 0 && step > 1) {
            const float* yb = sm + YBUF + (step & 1) * 32 + ks * 16;
            float y = blin;
#pragma unroll
            for (int i = 0; i < 16; ++i) y += yb[i];
            out[(step - 2) * NB + 2 * cta + ks] = y;
        }

        // (C) matvec: 4 gate rows x 2 batches, this k-half
        const float* hbase = sm + HBUF + (par ? HB_PAR : 0);
        const ulonglong2* H0 = (const ulonglong2*)(hbase + ks * KH);
        const ulonglong2* H1 = (const ulonglong2*)(hbase + HB_B + ks * KH);
        ull ai0 = 0, ai1 = 0, af0 = 0, af1 = 0, ag0 = 0, ag1 = 0, ao0 = 0, ao1 = 0;

#pragma unroll
        for (int c = 0; c < 16; ++c) {
            ulonglong2 hv0 = H0[c];
            ulonglong2 hv1 = H1[c];
            ulonglong2 w2  = W2[c];
            ulonglong2 w3  = W3[c];
            ull wia = wri[2 * c], wib = wri[2 * c + 1];
            ull wfa = wrf[2 * c], wfb = wrf[2 * c + 1];

            ai0 = ffma2(wia, hv0.x, ai0); ai0 = ffma2(wib, hv0.y, ai0);
            ai1 = ffma2(wia, hv1.x, ai1); ai1 = ffma2(wib, hv1.y, ai1);
            af0 = ffma2(wfa, hv0.x, af0); af0 = ffma2(wfb, hv0.y, af0);
            af1 = ffma2(wfa, hv1.x, af1); af1 = ffma2(wfb, hv1.y, af1);
            ag0 = ffma2(w2.x, hv0.x, ag0); ag0 = ffma2(w2.y, hv0.y, ag0);
            ag1 = ffma2(w2.x, hv1.x, ag1); ag1 = ffma2(w2.y, hv1.y, ag1);
            ao0 = ffma2(w3.x, hv0.x, ao0); ao0 = ffma2(w3.y, hv0.y, ao0);
            ao1 = ffma2(w3.x, hv1.x, ao1); ao1 = ffma2(w3.y, hv1.y, ao1);
        }

        // fold f32x2 + exchange k-halves with partner lane (t^1, same p)
        float gI, gF, gG, gO;
        {
            float2 f;
            f = upk2(ai0); float si0 = f.x + f.y;
            f = upk2(ai1); float si1 = f.x + f.y;
            f = upk2(af0); float sf0 = f.x + f.y;
            f = upk2(af1); float sf1 = f.x + f.y;
            f = upk2(ag0); float sg0 = f.x + f.y;
            f = upk2(ag1); float sg1 = f.x + f.y;
            f = upk2(ao0); float so0 = f.x + f.y;
            f = upk2(ao1); float so1 = f.x + f.y;
            gI = (ks ? si1 : si0) + __shfl_xor_sync(0xffffffffu, ks ? si0 : si1, 1);
            gF = (ks ? sf1 : sf0) + __shfl_xor_sync(0xffffffffu, ks ? sf0 : sf1, 1);
            gG = (ks ? sg1 : sg0) + __shfl_xor_sync(0xffffffffu, ks ? sg0 : sg1, 1);
            gO = (ks ? so1 : so0) + __shfl_xor_sync(0xffffffffu, ks ? so0 : so1, 1);
        }

        // (D) update (batch=ks, j=p)
        gI += biasv[0];
        gF += biasv[1];
        gG += biasv[2];
        gO += biasv[3];
        if (step == 0) {   // one-time correction, dead path afterwards
            gI += xb * wihv[0];
            gF += xb * wihv[1];
            gG += xb * wihv[2];
            gO += xb * wihv[3];
        }
        {
            float iv = siga(gI);
            float fv = siga(gF);
            float gv = tanha(gG);
            float ov = siga(gO);
            c_state = fv * c_state + iv * gv;
            float hn = ov * tanha(c_state);
            sm[hwr0 + (par ? 0 : HB_PAR)] = hn;   // next-parity h
            hn_prev = hn;
        }
        __syncthreads();   // next-parity HBUF (and YBUF writes) visible
    }

    // ---- epilogue: y for step T-1, then drain last two outputs --------------
    {
        float py = hn_prev * wlin_p;
        py += __shfl_xor_sync(0xffffffffu, py, 2);
        py += __shfl_xor_sync(0xffffffffu, py, 4);
        py += __shfl_xor_sync(0xffffffffu, py, 8);
        if ((lane & 14) == 0)
            sm[YBUF + ((T_STEPS - 1) & 1) * 32 + ks * 16 + (t >> 5) * 2 + (lane >> 4)] = py;
    }
    __syncthreads();
    if (p == 0) {
        const float* yb0 = sm + YBUF + ((T_STEPS - 2) & 1) * 32 + ks * 16;
        const float* yb1 = sm + YBUF + ((T_STEPS - 1) & 1) * 32 + ks * 16;
        float y0 = blin, y1 = blin;
#pragma unroll
        for (int i = 0; i < 16; ++i) { y0 += yb0[i]; y1 += yb1[i]; }
        out[(T_STEPS - 2) * NB + 2 * cta + ks] = y0;
        out[(T_STEPS - 1) * NB + 2 * cta + ks] = y1;
    }
}

extern "C" void kernel_launch(void* const* d_in, const int* in_sizes, int n_in,
                              void* d_out, int out_size) {
    // metadata order: input, label, h0, W_ih, W_hh, b_ih, b_hh, W_lin, b_lin
    const int*   label  = (const int*)  d_in[1];
    const float* h0     = (const float*)d_in[2];
    const float* W_ih   = (const float*)d_in[3];
    const float* W_hh   = (const float*)d_in[4];
    const float* b_ih   = (const float*)d_in[5];
    const float* b_hh   = (const float*)d_in[6];
    const float* W_lin  = (const float*)d_in[7];
    const float* b_lin  = (const float*)d_in[8];
    float* out = (float*)d_out;

    cudaFuncSetAttribute(lstm_seq_kernel,
                         cudaFuncAttributeMaxDynamicSharedMemorySize, SMEM_BYTES);
    lstm_seq_kernel<<<128, THREADS, SMEM_BYTES>>>(out, label, h0, W_ih, W_hh,
                                                  b_ih, b_hh, W_lin, b_lin);
}

// round 10
// speedup vs baseline: 1.2143x; 1.0670x over previous
#include <cuda_runtime.h>

// ---------------------------------------------------------------------------
// Persistent fused LSTM, feedback algebraically absorbed:
//   W_eff = W_hh + W_ih (outer) W_lin,  b_eff = b_ih + b_hh + W_ih * b_lin
// 128 CTAs x 256 threads; CTA owns batches (2c, 2c+1).
// Unit-owner mapping: thread (p=t>>1, ks=t&1) computes gates {i,f,g,o} of
// unit p, k-half ks, both batches; xor1 completes sums; same thread updates
// (batch=ks, j=p). ONE barrier/step; y-reduction deferred past the barrier.
// R9: first 16 floats of each k-half of the g,o rows also moved to registers
// (+8 ull) -> SMEM weight traffic 128->112 KB/step (crossbar floor -12.5%).
// ---------------------------------------------------------------------------

typedef unsigned long long ull;

#define THREADS 256
#define T_STEPS 2048
#define NB      256

// SMEM layout (float offsets)
#define KH       68                    // k-half stride (64 + 4 pad)
#define W_PITCH  136                   // weight row pitch -> LDS phases hit granules 0..7
#define WS_OFF   0                     // 256 rows (g,o gates) x 136 = 34816
#define HBUF     34816                 // [2 parity][2 batch x 144]
#define HB_B     144
#define HB_PAR   288
#define YBUF     (HBUF + 2*HB_PAR)     // [2 slot][2 batch][16]
#define SMEM_FLOATS (YBUF + 64)
#define SMEM_BYTES  (SMEM_FLOATS * 4)

__device__ __forceinline__ ull pk2(float x, float y) {
    ull r; asm("mov.b64 %0, {%1, %2};" : "=l"(r) : "f"(x), "f"(y)); return r;
}
__device__ __forceinline__ float2 upk2(ull v) {
    float2 f; asm("mov.b64 {%0, %1}, %2;" : "=f"(f.x), "=f"(f.y) : "l"(v)); return f;
}
__device__ __forceinline__ ull ffma2(ull a, ull b, ull c) {
    ull d; asm("fma.rn.f32x2 %0, %1, %2, %3;" : "=l"(d) : "l"(a), "l"(b), "l"(c)); return d;
}
__device__ __forceinline__ float tanha(float x) {
    float y; asm("tanh.approx.f32 %0, %1;" : "=f"(y) : "f"(x)); return y;
}
__device__ __forceinline__ float siga(float x) {
    return fmaf(0.5f, tanha(0.5f * x), 0.5f);
}

__global__ void __launch_bounds__(THREADS, 1)
lstm_seq_kernel(float* __restrict__ out,
                const int*   __restrict__ label,
                const float* __restrict__ h0,
                const float* __restrict__ W_ih,
                const float* __restrict__ W_hh,
                const float* __restrict__ b_ih,
                const float* __restrict__ b_hh,
                const float* __restrict__ W_lin,
                const float* __restrict__ b_lin)
{
    extern __shared__ float sm[];
    const int t    = threadIdx.x;
    const int cta  = blockIdx.x;
    const int p    = t >> 1;      // hidden unit 0..127
    const int ks   = t & 1;       // k half == batch this thread updates
    const int lane = t & 31;
    const float blin = b_lin[0];

    // ---- one-time init -----------------------------------------------------
    // SMEM weights: effective rows 256..511 (g,o gates), rank-1 folded in.
    // (First 16 floats of each k-half also live in regs; SMEM copy harmless.)
    for (int idx = t; idx < 256 * 128; idx += THREADS) {
        int r = idx >> 7, k = idx & 127;
        sm[WS_OFF + r * W_PITCH + (k >> 6) * KH + (k & 63)] =
            W_hh[(256 + r) * 128 + k] + W_ih[256 + r] * W_lin[k];
    }
    {   // initial h -> parity 0
        int b = t >> 7, j = t & 127;
        int lab = label[2 * cta + b];
        sm[HBUF + b * HB_B + (j >> 6) * KH + (j & 63)] = h0[lab * 128 + j];
    }

    // Register weights: effective rows p (i), 128+p (f) full k-half, plus the
    // first 16 floats of the k-half of rows 256+p (g) and 384+p (o).
    ull wri[32], wrf[32], wgx[8], wox[8];
    {
        const float2* s0 = (const float2*)(W_hh + p * 128 + ks * 64);
        const float2* s1 = (const float2*)(W_hh + (128 + p) * 128 + ks * 64);
        const float2* s2 = (const float2*)(W_hh + (256 + p) * 128 + ks * 64);
        const float2* s3 = (const float2*)(W_hh + (384 + p) * 128 + ks * 64);
        const float2* wl = (const float2*)(W_lin + ks * 64);
        const float wih_i = W_ih[p], wih_f = W_ih[128 + p];
        const float wih_g = W_ih[256 + p], wih_o = W_ih[384 + p];
#pragma unroll
        for (int c = 0; c < 32; ++c) {
            float2 a = s0[c], b = s1[c], w = wl[c];
            wri[c] = pk2(fmaf(wih_i, w.x, a.x), fmaf(wih_i, w.y, a.y));
            wrf[c] = pk2(fmaf(wih_f, w.x, b.x), fmaf(wih_f, w.y, b.y));
        }
#pragma unroll
        for (int c = 0; c < 8; ++c) {
            float2 g = s2[c], o = s3[c], w = wl[c];
            wgx[c] = pk2(fmaf(wih_g, w.x, g.x), fmaf(wih_g, w.y, g.y));
            wox[c] = pk2(fmaf(wih_o, w.x, o.x), fmaf(wih_o, w.y, o.y));
        }
    }

    // per-unit constants
    float biasv[4], wihv[4];
    {
        int rows[4] = {p, 128 + p, 256 + p, 384 + p};
#pragma unroll
        for (int q = 0; q < 4; ++q) {
            wihv[q]  = W_ih[rows[q]];
            biasv[q] = b_ih[rows[q]] + b_hh[rows[q]] + wihv[q] * blin;
        }
    }
    const float wlin_p = W_lin[p];
    float c_state = 0.0f;
    float hn_prev = 0.0f;

    __syncthreads();

    // step-0 correction: xb0 = -(W_lin . h_init[ks] + b_lin)
    float xb;
    {
        float acc = 0.0f;
        const float* hb = sm + HBUF + ks * HB_B;
#pragma unroll 8
        for (int j = 0; j < 128; ++j)
            acc = fmaf(hb[(j >> 6) * KH + (j & 63)], W_lin[j], acc);
        xb = -(acc + blin);
    }

    // constant pointers (SMEM weight loads start at c=2 of the k-half)
    const ulonglong2* W2 = (const ulonglong2*)(sm + WS_OFF + p * W_PITCH + ks * KH);
    const ulonglong2* W3 = (const ulonglong2*)(sm + WS_OFF + (128 + p) * W_PITCH + ks * KH);
    const int hwr0 = HBUF + ks * HB_B + (p >> 6) * KH + (p & 63);

    // ---- 2048-step recurrence: ONE barrier per step -------------------------
    for (int step = 0; step < T_STEPS; ++step) {
        const int par = step & 1;

        // (A) y-reduction for PREVIOUS step's h — overlaps the matvec's LDS
        if (step > 0) {
            float py = hn_prev * wlin_p;
            py += __shfl_xor_sync(0xffffffffu, py, 2);
            py += __shfl_xor_sync(0xffffffffu, py, 4);
            py += __shfl_xor_sync(0xffffffffu, py, 8);
            if ((lane & 14) == 0)   // lanes 0,1,16,17
                sm[YBUF + ((step - 1) & 1) * 32 + ks * 16 + (t >> 5) * 2 + (lane >> 4)] = py;
        }
        // (B) out-store for step-2 (off critical path; p==0 threads only)
        if (p == 0 && step > 1) {
            const float4* yb = (const float4*)(sm + YBUF + (step & 1) * 32 + ks * 16);
            float4 y0 = yb[0], y1 = yb[1], y2 = yb[2], y3 = yb[3];
            float y = ((y0.x + y0.y) + (y0.z + y0.w)) + ((y1.x + y1.y) + (y1.z + y1.w))
                    + ((y2.x + y2.y) + (y2.z + y2.w)) + ((y3.x + y3.y) + (y3.z + y3.w)) + blin;
            out[(step - 2) * NB + 2 * cta + ks] = y;
        }

        // (C) matvec: 4 gate rows x 2 batches, this k-half
        const float* hbase = sm + HBUF + (par ? HB_PAR : 0);
        const ulonglong2* H0 = (const ulonglong2*)(hbase + ks * KH);
        const ulonglong2* H1 = (const ulonglong2*)(hbase + HB_B + ks * KH);
        ull ai0 = 0, ai1 = 0, af0 = 0, af1 = 0, ag0 = 0, ag1 = 0, ao0 = 0, ao1 = 0;

        // c = 0,1: g,o weights from registers
#pragma unroll
        for (int c = 0; c < 2; ++c) {
            ulonglong2 hv0 = H0[c];
            ulonglong2 hv1 = H1[c];
            ull wia = wri[2 * c], wib = wri[2 * c + 1];
            ull wfa = wrf[2 * c], wfb = wrf[2 * c + 1];
            ull wga = wgx[2 * c], wgb = wgx[2 * c + 1];
            ull woa = wox[2 * c], wob = wox[2 * c + 1];

            ai0 = ffma2(wia, hv0.x, ai0); ai0 = ffma2(wib, hv0.y, ai0);
            ai1 = ffma2(wia, hv1.x, ai1); ai1 = ffma2(wib, hv1.y, ai1);
            af0 = ffma2(wfa, hv0.x, af0); af0 = ffma2(wfb, hv0.y, af0);
            af1 = ffma2(wfa, hv1.x, af1); af1 = ffma2(wfb, hv1.y, af1);
            ag0 = ffma2(wga, hv0.x, ag0); ag0 = ffma2(wgb, hv0.y, ag0);
            ag1 = ffma2(wga, hv1.x, ag1); ag1 = ffma2(wgb, hv1.y, ag1);
            ao0 = ffma2(woa, hv0.x, ao0); ao0 = ffma2(wob, hv0.y, ao0);
            ao1 = ffma2(woa, hv1.x, ao1); ao1 = ffma2(wob, hv1.y, ao1);
        }
        // c = 2..15: g,o weights streamed from SMEM
#pragma unroll
        for (int c = 2; c < 16; ++c) {
            ulonglong2 hv0 = H0[c];
            ulonglong2 hv1 = H1[c];
            ulonglong2 w2  = W2[c];
            ulonglong2 w3  = W3[c];
            ull wia = wri[2 * c], wib = wri[2 * c + 1];
            ull wfa = wrf[2 * c], wfb = wrf[2 * c + 1];

            ai0 = ffma2(wia, hv0.x, ai0); ai0 = ffma2(wib, hv0.y, ai0);
            ai1 = ffma2(wia, hv1.x, ai1); ai1 = ffma2(wib, hv1.y, ai1);
            af0 = ffma2(wfa, hv0.x, af0); af0 = ffma2(wfb, hv0.y, af0);
            af1 = ffma2(wfa, hv1.x, af1); af1 = ffma2(wfb, hv1.y, af1);
            ag0 = ffma2(w2.x, hv0.x, ag0); ag0 = ffma2(w2.y, hv0.y, ag0);
            ag1 = ffma2(w2.x, hv1.x, ag1); ag1 = ffma2(w2.y, hv1.y, ag1);
            ao0 = ffma2(w3.x, hv0.x, ao0); ao0 = ffma2(w3.y, hv0.y, ao0);
            ao1 = ffma2(w3.x, hv1.x, ao1); ao1 = ffma2(w3.y, hv1.y, ao1);
        }

        // fold f32x2 + exchange k-halves with partner lane (t^1, same p)
        float gI, gF, gG, gO;
        {
            float2 f;
            f = upk2(ai0); float si0 = f.x + f.y;
            f = upk2(ai1); float si1 = f.x + f.y;
            f = upk2(af0); float sf0 = f.x + f.y;
            f = upk2(af1); float sf1 = f.x + f.y;
            f = upk2(ag0); float sg0 = f.x + f.y;
            f = upk2(ag1); float sg1 = f.x + f.y;
            f = upk2(ao0); float so0 = f.x + f.y;
            f = upk2(ao1); float so1 = f.x + f.y;
            gI = (ks ? si1 : si0) + __shfl_xor_sync(0xffffffffu, ks ? si0 : si1, 1);
            gF = (ks ? sf1 : sf0) + __shfl_xor_sync(0xffffffffu, ks ? sf0 : sf1, 1);
            gG = (ks ? sg1 : sg0) + __shfl_xor_sync(0xffffffffu, ks ? sg0 : sg1, 1);
            gO = (ks ? so1 : so0) + __shfl_xor_sync(0xffffffffu, ks ? so0 : so1, 1);
        }

        // (D) update (batch=ks, j=p)
        gI += biasv[0];
        gF += biasv[1];
        gG += biasv[2];
        gO += biasv[3];
        if (step == 0) {   // one-time correction, dead path afterwards
            gI += xb * wihv[0];
            gF += xb * wihv[1];
            gG += xb * wihv[2];
            gO += xb * wihv[3];
        }
        {
            float iv = siga(gI);
            float fv = siga(gF);
            float gv = tanha(gG);
            float ov = siga(gO);
            c_state = fv * c_state + iv * gv;
            float hn = ov * tanha(c_state);
            sm[hwr0 + (par ? 0 : HB_PAR)] = hn;   // next-parity h
            hn_prev = hn;
        }
        __syncthreads();   // next-parity HBUF (and YBUF writes) visible
    }

    // ---- epilogue: y for step T-1, then drain last two outputs --------------
    {
        float py = hn_prev * wlin_p;
        py += __shfl_xor_sync(0xffffffffu, py, 2);
        py += __shfl_xor_sync(0xffffffffu, py, 4);
        py += __shfl_xor_sync(0xffffffffu, py, 8);
        if ((lane & 14) == 0)
            sm[YBUF + ((T_STEPS - 1) & 1) * 32 + ks * 16 + (t >> 5) * 2 + (lane >> 4)] = py;
    }
    __syncthreads();
    if (p == 0) {
        const float* yb0 = sm + YBUF + ((T_STEPS - 2) & 1) * 32 + ks * 16;
        const float* yb1 = sm + YBUF + ((T_STEPS - 1) & 1) * 32 + ks * 16;
        float y0 = blin, y1 = blin;
#pragma unroll
        for (int i = 0; i < 16; ++i) { y0 += yb0[i]; y1 += yb1[i]; }
        out[(T_STEPS - 2) * NB + 2 * cta + ks] = y0;
        out[(T_STEPS - 1) * NB + 2 * cta + ks] = y1;
    }
}

extern "C" void kernel_launch(void* const* d_in, const int* in_sizes, int n_in,
                              void* d_out, int out_size) {
    // metadata order: input, label, h0, W_ih, W_hh, b_ih, b_hh, W_lin, b_lin
    const int*   label  = (const int*)  d_in[1];
    const float* h0     = (const float*)d_in[2];
    const float* W_ih   = (const float*)d_in[3];
    const float* W_hh   = (const float*)d_in[4];
    const float* b_ih   = (const float*)d_in[5];
    const float* b_hh   = (const float*)d_in[6];
    const float* W_lin  = (const float*)d_in[7];
    const float* b_lin  = (const float*)d_in[8];
    float* out = (float*)d_out;

    cudaFuncSetAttribute(lstm_seq_kernel,
                         cudaFuncAttributeMaxDynamicSharedMemorySize, SMEM_BYTES);
    lstm_seq_kernel<<<128, THREADS, SMEM_BYTES>>>(out, label, h0, W_ih, W_hh,
                                                  b_ih, b_hh, W_lin, b_lin);
}